// round 9
// baseline (speedup 1.0000x reference)
#include <cuda_runtime.h>
#include <cuda_bf16.h>
#include <cstdint>
#include <math.h>

#define BATCH 4
#define SEQ   4096
#define DIM   1024
#define MTOT  (BATCH * SEQ)          // 16384
#define LN_EPS 1e-5f
#define SM_SCALE (1.0f / 32.0f)

// ---- GEMM tiling: 128x128 CTA tile, warp 64x32, KC=64, 3-stage pipeline ---
#define TM 128
#define TN 128
#define KC 64                        // bf16 K per chunk (128 B/row)
#define ROWB 144                     // 128 B data + 16 B pad
#define OFF_A 0
#define OFF_B 18432                  // 128 rows * 144 B
#define STAGE_BYTES 36864
#define NSTAGE 3
#define GEMM_SMEM (NSTAGE * STAGE_BYTES)   // 110592 (2 CTAs/SM: 221184 <= 228KB)

// ---------------------------------------------------------------------------
// Scratch (device globals: allocation-free rule)
// ---------------------------------------------------------------------------
__device__ __nv_bfloat16 g_emb_b[(size_t)MTOT * DIM];
__device__ __nv_bfloat16 g_w_b[(size_t)3 * DIM * DIM];
__device__ __nv_bfloat16 g_q_b[(size_t)MTOT * DIM];
__device__ __nv_bfloat16 g_k_b[(size_t)MTOT * DIM];
__device__ __nv_bfloat16 g_vt_b[(size_t)DIM * MTOT];        // V^T: [1024][16384]
__device__ __nv_bfloat16 g_s_b[(size_t)BATCH * SEQ * SEQ];  // scores bf16
__device__ __nv_bfloat16 g_p_b[(size_t)BATCH * SEQ * SEQ];  // probs bf16
__device__ float         g_att[(size_t)MTOT * DIM];

// ---------------------------------------------------------------------------
// Helpers
// ---------------------------------------------------------------------------
__device__ __forceinline__ uint32_t smem_u32(const void* p) {
    uint32_t a;
    asm("{ .reg .u64 t; cvta.to.shared.u64 t, %1; cvt.u32.u64 %0, t; }"
        : "=r"(a) : "l"(p));
    return a;
}

__device__ __forceinline__ void cp16(uint32_t dst, const void* src) {
    size_t g = __cvta_generic_to_global(src);
    asm volatile("cp.async.cg.shared.global [%0], [%1], 16;" :: "r"(dst), "l"(g) : "memory");
}
__device__ __forceinline__ void cp_commit() {
    asm volatile("cp.async.commit_group;" ::: "memory");
}
template <int N> __device__ __forceinline__ void cp_wait() {
    asm volatile("cp.async.wait_group %0;" :: "n"(N) : "memory");
}

__device__ __forceinline__ void ldm4(uint32_t& r0, uint32_t& r1, uint32_t& r2, uint32_t& r3,
                                     uint32_t addr) {
    asm volatile("ldmatrix.sync.aligned.m8n8.x4.shared.b16 {%0,%1,%2,%3}, [%4];"
                 : "=r"(r0), "=r"(r1), "=r"(r2), "=r"(r3) : "r"(addr));
}

__device__ __forceinline__ void mma16816(float* d, const uint32_t* a, const uint32_t* b) {
    asm volatile(
        "mma.sync.aligned.m16n8k16.row.col.f32.bf16.bf16.f32 "
        "{%0,%1,%2,%3}, {%4,%5,%6,%7}, {%8,%9}, {%0,%1,%2,%3};"
        : "+f"(d[0]), "+f"(d[1]), "+f"(d[2]), "+f"(d[3])
        : "r"(a[0]), "r"(a[1]), "r"(a[2]), "r"(a[3]), "r"(b[0]), "r"(b[1]));
}

__device__ __forceinline__ uint32_t pack_bf2(float a, float b) {
    __nv_bfloat162 v = __floats2bfloat162_rn(a, b);
    return *(uint32_t*)&v;
}

// ---------------------------------------------------------------------------
// bf16 mma.sync GEMM (NT): C[m,n] = alpha * sum_k A[m,k]*B[n,k] (+bias)
// A: [M,K] row stride K; B: rows indexed by n, row stride ldB.
// CTA tile 128x128, chunk K=64, 3-stage cp.async pipeline, 256 threads
// (8 warps, warp tile 64x32), register double-buffered fragments.
// Output fp32 (Cf) or bf16 (Cb). bias_row: bias indexed by m instead of n.
// ---------------------------------------------------------------------------
__global__ void __launch_bounds__(256, 2)
gemm_mma(const __nv_bfloat16* __restrict__ A_, const __nv_bfloat16* __restrict__ B_,
         const float* __restrict__ bias, int bias_row,
         float* __restrict__ Cf, __nv_bfloat16* __restrict__ Cb,
         int N, int K, int ldB, float alpha,
         size_t sA, size_t sB, size_t sC)
{
    extern __shared__ char smem[];
    const uint32_t sb = smem_u32(smem);
    const int tid = threadIdx.x, lane = tid & 31, wid = tid >> 5;
    const int warp_m = wid & 1;       // 0..1 (64 rows each)
    const int warp_n = wid >> 1;      // 0..3 (32 cols each)
    const int m0 = blockIdx.y * TM, n0 = blockIdx.x * TN;

    const __nv_bfloat16* A = A_ + blockIdx.z * sA;
    const __nv_bfloat16* B = B_ + blockIdx.z * sB;

    // gmem -> smem: thread t loads row t/2, 64B half (t&1), 4 x cp16 each tile
    const int lr = tid >> 1;
    const int lh = tid & 1;

    auto load_chunk = [&](int stage, int kc) {
        const uint32_t st = sb + stage * STAGE_BYTES;
        const uint32_t dofs = (uint32_t)lr * ROWB + lh * 64;
        const size_t ao = (size_t)(m0 + lr) * K + (size_t)kc * KC + lh * 32;
        const char* pA = (const char*)(A + ao);
#pragma unroll
        for (int j = 0; j < 4; ++j)
            cp16(st + OFF_A + dofs + j * 16, pA + j * 16);
        const size_t bo = (size_t)(n0 + lr) * ldB + (size_t)kc * KC + lh * 32;
        const char* pB = (const char*)(B + bo);
#pragma unroll
        for (int j = 0; j < 4; ++j)
            cp16(st + OFF_B + dofs + j * 16, pB + j * 16);
        cp_commit();
    };

    // ldmatrix per-thread base offsets (bytes); k-step ks adds ks*32
    const uint32_t aoff = (uint32_t)((warp_m * 64 + (lane & 15)) * ROWB + ((lane >> 4) & 1) * 16);
    const uint32_t boff = (uint32_t)((warp_n * 32 + ((lane >> 4) & 1) * 8 + (lane & 7)) * ROWB
                                     + ((lane >> 3) & 1) * 16);

    float acc[4][4][4];
#pragma unroll
    for (int mt = 0; mt < 4; ++mt)
#pragma unroll
        for (int nt = 0; nt < 4; ++nt)
#pragma unroll
            for (int r = 0; r < 4; ++r) acc[mt][nt][r] = 0.f;

    const int nk = K / KC;
    load_chunk(0, 0);
    load_chunk(1, 1);

    // double-buffered fragments
    uint32_t afr[2][4][4], bfr[2][4][2];

    auto load_frags = [&](int buf, uint32_t abase, uint32_t bbase, int ks) {
#pragma unroll
        for (int pr = 0; pr < 2; ++pr) {
            uint32_t r0, r1, r2, r3;
            ldm4(r0, r1, r2, r3, bbase + pr * 2304 + ks * 32);
            bfr[buf][pr*2][0] = r0; bfr[buf][pr*2][1] = r1;
            bfr[buf][pr*2+1][0] = r2; bfr[buf][pr*2+1][1] = r3;
        }
#pragma unroll
        for (int mt = 0; mt < 4; ++mt)
            ldm4(afr[buf][mt][0], afr[buf][mt][1], afr[buf][mt][2], afr[buf][mt][3],
                 abase + mt * 2304 + ks * 32);
    };

    auto do_mmas = [&](int buf) {
#pragma unroll
        for (int mt = 0; mt < 4; ++mt)
#pragma unroll
            for (int nt = 0; nt < 4; ++nt)
                mma16816(acc[mt][nt], afr[buf][mt], bfr[buf][nt]);
    };

    for (int i = 0; i < nk; ++i) {
        const int cur = i % NSTAGE;
        cp_wait<1>();              // chunk i resident
        __syncthreads();           // all warps done with the stage being overwritten
        if (i + 2 < nk) load_chunk((i + 2) % NSTAGE, i + 2);
        else            cp_commit();

        const uint32_t st    = sb + cur * STAGE_BYTES;
        const uint32_t abase = st + OFF_A + aoff;
        const uint32_t bbase = st + OFF_B + boff;

        load_frags(0, abase, bbase, 0);
#pragma unroll
        for (int ks = 0; ks < 4; ++ks) {
            if (ks + 1 < 4) load_frags((ks + 1) & 1, abase, bbase, ks + 1);
            do_mmas(ks & 1);
        }
    }

    // Epilogue: frag (tr, c2): d0,d1 -> row tr, d2,d3 -> row tr+8
    const int tr = lane >> 2;
    const int c2 = (lane & 3) * 2;
#pragma unroll
    for (int mt = 0; mt < 4; ++mt) {
#pragma unroll
        for (int nt = 0; nt < 4; ++nt) {
            const int mrow = m0 + warp_m * 64 + mt * 16 + tr;
            const int ncol = n0 + warp_n * 32 + nt * 8 + c2;
            float x0 = acc[mt][nt][0] * alpha;
            float x1 = acc[mt][nt][1] * alpha;
            float x2 = acc[mt][nt][2] * alpha;
            float x3 = acc[mt][nt][3] * alpha;
            if (bias) {
                if (bias_row) {
                    const float b0 = __ldg(bias + mrow), b1 = __ldg(bias + mrow + 8);
                    x0 += b0; x1 += b0; x2 += b1; x3 += b1;
                } else {
                    const float b0 = __ldg(bias + ncol), b1 = __ldg(bias + ncol + 1);
                    x0 += b0; x1 += b1; x2 += b0; x3 += b1;
                }
            }
            if (Cf) {
                float* c0 = Cf + blockIdx.z * sC + (size_t)mrow * N + ncol;
                *(float2*)c0                   = make_float2(x0, x1);
                *(float2*)(c0 + (size_t)8 * N) = make_float2(x2, x3);
            } else {
                __nv_bfloat16* c0 = Cb + blockIdx.z * sC + (size_t)mrow * N + ncol;
                *(uint32_t*)c0                   = pack_bf2(x0, x1);
                *(uint32_t*)(c0 + (size_t)8 * N) = pack_bf2(x2, x3);
            }
        }
    }
}

// ---------------------------------------------------------------------------
// fp32 -> bf16 convert; gridDim.z selects among up to 3 src/dst pairs
// ---------------------------------------------------------------------------
__global__ void __launch_bounds__(256)
cvt3_kernel(const float4* __restrict__ in0, uint2* __restrict__ out0,
            const float4* __restrict__ in1, uint2* __restrict__ out1,
            const float4* __restrict__ in2, uint2* __restrict__ out2, int n4)
{
    const int i = blockIdx.x * 256 + threadIdx.x;
    if (i >= n4) return;
    const float4* in; uint2* out;
    if (blockIdx.z == 0)      { in = in0; out = out0; }
    else if (blockIdx.z == 1) { in = in1; out = out1; }
    else                      { in = in2; out = out2; }
    float4 x = in[i];
    uint2 o;
    o.x = pack_bf2(x.x, x.y);
    o.y = pack_bf2(x.z, x.w);
    out[i] = o;
}

// ---------------------------------------------------------------------------
// Row softmax over SEQ from bf16 scores (folds 1/sqrt(D)); emits bf16 P.
// ---------------------------------------------------------------------------
__global__ void __launch_bounds__(256)
softmax_kernel(const __nv_bfloat16* __restrict__ S, __nv_bfloat16* __restrict__ P)
{
    __shared__ float sh[8];
    const size_t rb = (size_t)blockIdx.x * SEQ;
    const int t = threadIdx.x, lane = t & 31, wrp = t >> 5;

    uint4 u0 = *(const uint4*)(S + rb + t * 8);
    uint4 u1 = *(const uint4*)(S + rb + 2048 + t * 8);

    float f[16];
    {
        const uint32_t* w0 = (const uint32_t*)&u0;
        const uint32_t* w1 = (const uint32_t*)&u1;
#pragma unroll
        for (int j = 0; j < 4; ++j) {
            float2 a = __bfloat1622float2(*(const __nv_bfloat162*)&w0[j]);
            f[j*2]   = a.x; f[j*2+1] = a.y;
            float2 b = __bfloat1622float2(*(const __nv_bfloat162*)&w1[j]);
            f[8+j*2] = b.x; f[8+j*2+1] = b.y;
        }
    }

    float mx = -1e30f;
#pragma unroll
    for (int j = 0; j < 16; ++j) mx = fmaxf(mx, f[j]);
#pragma unroll
    for (int o = 16; o > 0; o >>= 1) mx = fmaxf(mx, __shfl_xor_sync(0xffffffffu, mx, o));
    if (lane == 0) sh[wrp] = mx;
    __syncthreads();
    float m_all = sh[0];
#pragma unroll
    for (int w = 1; w < 8; ++w) m_all = fmaxf(m_all, sh[w]);
    __syncthreads();

    float sum = 0.f;
#pragma unroll
    for (int j = 0; j < 16; ++j) {
        f[j] = __expf((f[j] - m_all) * SM_SCALE);
        sum += f[j];
    }
#pragma unroll
    for (int o = 16; o > 0; o >>= 1) sum += __shfl_xor_sync(0xffffffffu, sum, o);
    if (lane == 0) sh[wrp] = sum;
    __syncthreads();
    float s_all = 0.f;
#pragma unroll
    for (int w = 0; w < 8; ++w) s_all += sh[w];
    const float inv = 1.0f / s_all;

    uint4 o0, o1;
    uint32_t* w0 = (uint32_t*)&o0;
    uint32_t* w1 = (uint32_t*)&o1;
#pragma unroll
    for (int j = 0; j < 4; ++j) {
        w0[j] = pack_bf2(f[j*2] * inv,   f[j*2+1] * inv);
        w1[j] = pack_bf2(f[8+j*2] * inv, f[8+j*2+1] * inv);
    }
    *(uint4*)(P + rb + t * 8)        = o0;
    *(uint4*)(P + rb + 2048 + t * 8) = o1;
}

// ---------------------------------------------------------------------------
// Residual + LayerNorm over D=1024.
// ---------------------------------------------------------------------------
__global__ void __launch_bounds__(256)
ln_kernel(const float* __restrict__ emb, const float* __restrict__ att,
          const float* __restrict__ gamma, const float* __restrict__ beta,
          float* __restrict__ out)
{
    __shared__ float shs[8];
    __shared__ float shq[8];
    const size_t base = (size_t)blockIdx.x * DIM;
    const int t = threadIdx.x, lane = t & 31, wrp = t >> 5;

    float4 e = *(const float4*)(emb + base + t * 4);
    float4 a = *(const float4*)(att + base + t * 4);
    float4 x;
    x.x = e.x + a.x; x.y = e.y + a.y; x.z = e.z + a.z; x.w = e.w + a.w;

    float s  = x.x + x.y + x.z + x.w;
    float sq = x.x*x.x + x.y*x.y + x.z*x.z + x.w*x.w;
#pragma unroll
    for (int o = 16; o > 0; o >>= 1) {
        s  += __shfl_xor_sync(0xffffffffu, s,  o);
        sq += __shfl_xor_sync(0xffffffffu, sq, o);
    }
    if (lane == 0) { shs[wrp] = s; shq[wrp] = sq; }
    __syncthreads();
    s = 0.f; sq = 0.f;
#pragma unroll
    for (int w = 0; w < 8; ++w) { s += shs[w]; sq += shq[w]; }

    const float mu   = s * (1.0f / (float)DIM);
    const float var  = sq * (1.0f / (float)DIM) - mu * mu;
    const float rstd = rsqrtf(var + LN_EPS);

    float4 g  = *(const float4*)(gamma + t * 4);
    float4 bt = *(const float4*)(beta  + t * 4);
    float4 r;
    r.x = g.x * (x.x - mu) * rstd + bt.x;
    r.y = g.y * (x.y - mu) * rstd + bt.y;
    r.z = g.z * (x.z - mu) * rstd + bt.z;
    r.w = g.w * (x.w - mu) * rstd + bt.w;
    *(float4*)(out + base + t * 4) = r;
}

// ---------------------------------------------------------------------------
// Launch
// ---------------------------------------------------------------------------
extern "C" void kernel_launch(void* const* d_in, const int* in_sizes, int n_in,
                              void* d_out, int out_size)
{
    (void)in_sizes; (void)n_in; (void)out_size;
    const float* emb   = (const float*)d_in[0];
    const float* Wq    = (const float*)d_in[4];
    const float* bq    = (const float*)d_in[5];
    const float* Wk    = (const float*)d_in[6];
    const float* bk    = (const float*)d_in[7];
    const float* Wv    = (const float*)d_in[8];
    const float* bv    = (const float*)d_in[9];
    const float* gamma = (const float*)d_in[10];
    const float* beta  = (const float*)d_in[11];
    float* out = (float*)d_out;

    void* p;
    __nv_bfloat16 *emb_b, *w_b, *q_b, *k_b, *vt_b, *s_b, *p_b;
    float *att;
    cudaGetSymbolAddress(&p, g_emb_b); emb_b = (__nv_bfloat16*)p;
    cudaGetSymbolAddress(&p, g_w_b);   w_b   = (__nv_bfloat16*)p;
    cudaGetSymbolAddress(&p, g_q_b);   q_b   = (__nv_bfloat16*)p;
    cudaGetSymbolAddress(&p, g_k_b);   k_b   = (__nv_bfloat16*)p;
    cudaGetSymbolAddress(&p, g_vt_b);  vt_b  = (__nv_bfloat16*)p;
    cudaGetSymbolAddress(&p, g_s_b);   s_b   = (__nv_bfloat16*)p;
    cudaGetSymbolAddress(&p, g_p_b);   p_b   = (__nv_bfloat16*)p;
    cudaGetSymbolAddress(&p, g_att);   att   = (float*)p;

    cudaFuncSetAttribute(gemm_mma, cudaFuncAttributeMaxDynamicSharedMemorySize, GEMM_SMEM);

    // Convert inputs to bf16: emb (big) + 3 weights in one z-batched launch
    const int n4e = MTOT * DIM / 4;
    cvt3_kernel<<<dim3((n4e + 255) / 256, 1, 1), 256>>>(
        (const float4*)emb, (uint2*)emb_b, nullptr, nullptr, nullptr, nullptr, n4e);
    const int n4w = DIM * DIM / 4;
    cvt3_kernel<<<dim3((n4w + 255) / 256, 1, 3), 256>>>(
        (const float4*)Wq, (uint2*)(w_b),
        (const float4*)Wk, (uint2*)(w_b + DIM * DIM),
        (const float4*)Wv, (uint2*)(w_b + 2 * DIM * DIM), n4w);

    const dim3 blk(256);

    // Q,K projections: [16384,1024] x [1024,1024]^T + bias -> bf16
    const dim3 gq(DIM / TN, MTOT / TM, 1);
    gemm_mma<<<gq, blk, GEMM_SMEM>>>(emb_b, w_b,             bq, 0, nullptr, q_b,
                                     DIM, DIM, DIM, 1.f, 0, 0, 0);
    gemm_mma<<<gq, blk, GEMM_SMEM>>>(emb_b, w_b + DIM * DIM, bk, 0, nullptr, k_b,
                                     DIM, DIM, DIM, 1.f, 0, 0, 0);

    // V^T directly: Vt[d][n] = sum_k Wv[d,k]*emb[n,k] + bv[d]  (bias per row)
    const dim3 gv(MTOT / TN, DIM / TM, 1);
    gemm_mma<<<gv, blk, GEMM_SMEM>>>(w_b + 2 * DIM * DIM, emb_b, bv, 1, nullptr, vt_b,
                                     MTOT, DIM, DIM, 1.f, 0, 0, 0);

    // Scores: per-batch Q @ K^T -> bf16 (scale folded into softmax)
    const dim3 gs(SEQ / TN, SEQ / TM, BATCH);
    gemm_mma<<<gs, blk, GEMM_SMEM>>>(q_b, k_b, nullptr, 0, nullptr, s_b,
                                     SEQ, DIM, DIM, 1.f,
                                     (size_t)SEQ * DIM, (size_t)SEQ * DIM, (size_t)SEQ * SEQ);

    // Softmax rows -> bf16 P
    softmax_kernel<<<MTOT, 256>>>(s_b, p_b);

    // Attended: per-batch P @ V  (B = Vt rows, row stride MTOT, batch col offset SEQ)
    const dim3 gp(DIM / TN, SEQ / TM, BATCH);
    gemm_mma<<<gp, blk, GEMM_SMEM>>>(p_b, vt_b, nullptr, 0, att, nullptr,
                                     DIM, SEQ, MTOT, 1.f,
                                     (size_t)SEQ * SEQ, (size_t)SEQ, (size_t)SEQ * DIM);

    // Residual + LayerNorm
    ln_kernel<<<MTOT, 256>>>(emb, att, gamma, beta, out);
}

// round 10
// speedup vs baseline: 1.2635x; 1.2635x over previous
#include <cuda_runtime.h>
#include <cuda_bf16.h>
#include <cstdint>
#include <math.h>

#define BATCH 4
#define SEQ   4096
#define DIM   1024
#define MTOT  (BATCH * SEQ)          // 16384
#define LN_EPS 1e-5f
#define SM_SCALE (1.0f / 32.0f)

// ---- FP8 GEMM tiling: 128x128 CTA tile, warp 64x32, KC=64 fp8, 4 stages ---
#define TM 128
#define TN 128
#define KC 64                        // fp8 K per chunk (64 B/row)
#define ROWB 80                      // 64 B data + 16 B pad
#define OFF_A 0
#define OFF_B 10240                  // 128 rows * 80 B
#define STAGE_BYTES 20480
#define NSTAGE 4
#define GEMM_SMEM (NSTAGE * STAGE_BYTES)   // 81920 (2 CTAs/SM)

// ---------------------------------------------------------------------------
// Scratch (device globals: allocation-free rule)
// ---------------------------------------------------------------------------
__device__ uint8_t       g_emb8[(size_t)MTOT * DIM];
__device__ uint8_t       g_w8[(size_t)3 * DIM * DIM];       // scaled x32
__device__ uint8_t       g_q8[(size_t)MTOT * DIM];
__device__ uint8_t       g_k8[(size_t)MTOT * DIM];
__device__ uint8_t       g_vt8[(size_t)DIM * MTOT];         // V^T fp8
__device__ __nv_bfloat16 g_s_b[(size_t)BATCH * SEQ * SEQ];  // scores bf16
__device__ uint8_t       g_p8[(size_t)BATCH * SEQ * SEQ];   // probs fp8 x256
__device__ float         g_att[(size_t)MTOT * DIM];

// ---------------------------------------------------------------------------
// Helpers
// ---------------------------------------------------------------------------
__device__ __forceinline__ uint32_t smem_u32(const void* p) {
    uint32_t a;
    asm("{ .reg .u64 t; cvta.to.shared.u64 t, %1; cvt.u32.u64 %0, t; }"
        : "=r"(a) : "l"(p));
    return a;
}

__device__ __forceinline__ void cp16(uint32_t dst, const void* src) {
    size_t g = __cvta_generic_to_global(src);
    asm volatile("cp.async.cg.shared.global [%0], [%1], 16;" :: "r"(dst), "l"(g) : "memory");
}
__device__ __forceinline__ void cp_commit() {
    asm volatile("cp.async.commit_group;" ::: "memory");
}
template <int N> __device__ __forceinline__ void cp_wait() {
    asm volatile("cp.async.wait_group %0;" :: "n"(N) : "memory");
}

__device__ __forceinline__ void ldm4(uint32_t& r0, uint32_t& r1, uint32_t& r2, uint32_t& r3,
                                     uint32_t addr) {
    asm volatile("ldmatrix.sync.aligned.m8n8.x4.shared.b16 {%0,%1,%2,%3}, [%4];"
                 : "=r"(r0), "=r"(r1), "=r"(r2), "=r"(r3) : "r"(addr));
}

// fp8 e4m3 MMA: D[16x8] += A[16x32] * B[32x8]
__device__ __forceinline__ void mma_fp8(float* d, const uint32_t* a, const uint32_t* b) {
    asm volatile(
        "mma.sync.aligned.m16n8k32.row.col.f32.e4m3.e4m3.f32 "
        "{%0,%1,%2,%3}, {%4,%5,%6,%7}, {%8,%9}, {%0,%1,%2,%3};"
        : "+f"(d[0]), "+f"(d[1]), "+f"(d[2]), "+f"(d[3])
        : "r"(a[0]), "r"(a[1]), "r"(a[2]), "r"(a[3]), "r"(b[0]), "r"(b[1]));
}

__device__ __forceinline__ uint32_t pack_bf2(float a, float b) {
    __nv_bfloat162 v = __floats2bfloat162_rn(a, b);
    return *(uint32_t*)&v;
}

// packs {lo, hi} -> e4m3x2 (low byte = lo)
__device__ __forceinline__ uint16_t pack_f8_2(float lo, float hi) {
    uint16_t u;
    asm("cvt.rn.satfinite.e4m3x2.f32 %0, %1, %2;" : "=h"(u) : "f"(hi), "f"(lo));
    return u;
}
__device__ __forceinline__ uint32_t pack_f8_4(float a, float b, float c, float d) {
    return (uint32_t)pack_f8_2(a, b) | ((uint32_t)pack_f8_2(c, d) << 16);
}

// ---------------------------------------------------------------------------
// fp8 mma.sync GEMM (NT): C[m,n] = alpha * sum_k A[m,k]*B[n,k] (+bias)
// A: [M,K] fp8 row stride K; B: fp8 rows indexed by n, row stride ldB.
// CTA tile 128x128, chunk K=64 fp8, 4-stage cp.async pipeline, 256 threads
// (8 warps, warp tile 64x32). Out: fp32 (Cf) | bf16 (Cb) | fp8 (C8).
// bias_row: bias indexed by m instead of n.
// ---------------------------------------------------------------------------
__global__ void __launch_bounds__(256, 2)
gemm_fp8(const uint8_t* __restrict__ A_, const uint8_t* __restrict__ B_,
         const float* __restrict__ bias, int bias_row,
         float* __restrict__ Cf, __nv_bfloat16* __restrict__ Cb, uint8_t* __restrict__ C8,
         int N, int K, int ldB, float alpha,
         size_t sA, size_t sB, size_t sC)
{
    extern __shared__ char smem[];
    const uint32_t sb = smem_u32(smem);
    const int tid = threadIdx.x, lane = tid & 31, wid = tid >> 5;
    const int warp_m = wid & 1;       // 0..1 (64 rows each)
    const int warp_n = wid >> 1;      // 0..3 (32 cols each)
    const int m0 = blockIdx.y * TM, n0 = blockIdx.x * TN;

    const uint8_t* A = A_ + blockIdx.z * sA;
    const uint8_t* B = B_ + blockIdx.z * sB;

    // gmem -> smem: thread t loads row t/2, 32B half (t&1), 2 cp16 per tile
    const int lr = tid >> 1;
    const int lh = tid & 1;

    auto load_chunk = [&](int stage, int kc) {
        const uint32_t st = sb + stage * STAGE_BYTES;
        const uint32_t dofs = (uint32_t)lr * ROWB + lh * 32;
        const size_t ao = (size_t)(m0 + lr) * K + (size_t)kc * KC + lh * 32;
        const char* pA = (const char*)(A + ao);
        cp16(st + OFF_A + dofs,      pA);
        cp16(st + OFF_A + dofs + 16, pA + 16);
        const size_t bo = (size_t)(n0 + lr) * ldB + (size_t)kc * KC + lh * 32;
        const char* pB = (const char*)(B + bo);
        cp16(st + OFF_B + dofs,      pB);
        cp16(st + OFF_B + dofs + 16, pB + 16);
        cp_commit();
    };

    // ldmatrix per-thread base offsets (bytes); k32-step ks adds ks*32
    const uint32_t aoff = (uint32_t)((warp_m * 64 + (lane & 15)) * ROWB + ((lane >> 4) & 1) * 16);
    const uint32_t boff = (uint32_t)((warp_n * 32 + ((lane >> 4) & 1) * 8 + (lane & 7)) * ROWB
                                     + ((lane >> 3) & 1) * 16);

    float acc[4][4][4];
#pragma unroll
    for (int mt = 0; mt < 4; ++mt)
#pragma unroll
        for (int nt = 0; nt < 4; ++nt)
#pragma unroll
            for (int r = 0; r < 4; ++r) acc[mt][nt][r] = 0.f;

    const int nk = K / KC;
    load_chunk(0, 0);
    load_chunk(1, 1);
    load_chunk(2, 2);

    // double-buffered fragments
    uint32_t afr[2][4][4], bfr[2][4][2];

    auto load_frags = [&](int buf, uint32_t abase, uint32_t bbase, int ks) {
#pragma unroll
        for (int pr = 0; pr < 2; ++pr) {
            uint32_t r0, r1, r2, r3;
            ldm4(r0, r1, r2, r3, bbase + pr * 1280 + ks * 32);
            bfr[buf][pr*2][0] = r0; bfr[buf][pr*2][1] = r1;
            bfr[buf][pr*2+1][0] = r2; bfr[buf][pr*2+1][1] = r3;
        }
#pragma unroll
        for (int mt = 0; mt < 4; ++mt)
            ldm4(afr[buf][mt][0], afr[buf][mt][1], afr[buf][mt][2], afr[buf][mt][3],
                 abase + mt * 1280 + ks * 32);
    };

    auto do_mmas = [&](int buf) {
#pragma unroll
        for (int mt = 0; mt < 4; ++mt)
#pragma unroll
            for (int nt = 0; nt < 4; ++nt)
                mma_fp8(acc[mt][nt], afr[buf][mt], bfr[buf][nt]);
    };

    for (int i = 0; i < nk; ++i) {
        const int cur = i % NSTAGE;
        cp_wait<2>();              // chunk i resident
        __syncthreads();           // all warps done with the stage being overwritten
        if (i + 3 < nk) load_chunk((i + 3) % NSTAGE, i + 3);
        else            cp_commit();

        const uint32_t st    = sb + cur * STAGE_BYTES;
        const uint32_t abase = st + OFF_A + aoff;
        const uint32_t bbase = st + OFF_B + boff;

        load_frags(0, abase, bbase, 0);    // k32-step 0
        load_frags(1, abase, bbase, 1);    // k32-step 1 (overlaps step-0 MMAs)
        do_mmas(0);
        do_mmas(1);
    }

    // Epilogue: frag (tr, c2): d0,d1 -> row tr, d2,d3 -> row tr+8
    const int tr = lane >> 2;
    const int c2 = (lane & 3) * 2;
#pragma unroll
    for (int mt = 0; mt < 4; ++mt) {
#pragma unroll
        for (int nt = 0; nt < 4; ++nt) {
            const int mrow = m0 + warp_m * 64 + mt * 16 + tr;
            const int ncol = n0 + warp_n * 32 + nt * 8 + c2;
            float x0 = acc[mt][nt][0] * alpha;
            float x1 = acc[mt][nt][1] * alpha;
            float x2 = acc[mt][nt][2] * alpha;
            float x3 = acc[mt][nt][3] * alpha;
            if (bias) {
                if (bias_row) {
                    const float b0 = __ldg(bias + mrow), b1 = __ldg(bias + mrow + 8);
                    x0 += b0; x1 += b0; x2 += b1; x3 += b1;
                } else {
                    const float b0 = __ldg(bias + ncol), b1 = __ldg(bias + ncol + 1);
                    x0 += b0; x1 += b1; x2 += b0; x3 += b1;
                }
            }
            if (Cf) {
                float* c0 = Cf + blockIdx.z * sC + (size_t)mrow * N + ncol;
                *(float2*)c0                   = make_float2(x0, x1);
                *(float2*)(c0 + (size_t)8 * N) = make_float2(x2, x3);
            } else if (Cb) {
                __nv_bfloat16* c0 = Cb + blockIdx.z * sC + (size_t)mrow * N + ncol;
                *(uint32_t*)c0                   = pack_bf2(x0, x1);
                *(uint32_t*)(c0 + (size_t)8 * N) = pack_bf2(x2, x3);
            } else {
                uint8_t* c0 = C8 + blockIdx.z * sC + (size_t)mrow * N + ncol;
                *(uint16_t*)c0                   = pack_f8_2(x0, x1);
                *(uint16_t*)(c0 + (size_t)8 * N) = pack_f8_2(x2, x3);
            }
        }
    }
}

// ---------------------------------------------------------------------------
// fp32 -> fp8 convert with scale; gridDim.z selects among up to 3 pairs.
// 8 elements per thread.
// ---------------------------------------------------------------------------
__global__ void __launch_bounds__(256)
cvt8_kernel(const float4* __restrict__ in0, uint2* __restrict__ out0,
            const float4* __restrict__ in1, uint2* __restrict__ out1,
            const float4* __restrict__ in2, uint2* __restrict__ out2,
            float scale, int n8)
{
    const int i = blockIdx.x * 256 + threadIdx.x;
    if (i >= n8) return;
    const float4* in; uint2* out;
    if (blockIdx.z == 0)      { in = in0; out = out0; }
    else if (blockIdx.z == 1) { in = in1; out = out1; }
    else                      { in = in2; out = out2; }
    float4 x = in[i * 2];
    float4 y = in[i * 2 + 1];
    uint2 o;
    o.x = pack_f8_4(x.x * scale, x.y * scale, x.z * scale, x.w * scale);
    o.y = pack_f8_4(y.x * scale, y.y * scale, y.z * scale, y.w * scale);
    out[i] = o;
}

// ---------------------------------------------------------------------------
// Row softmax over SEQ from bf16 scores (folds 1/sqrt(D)); emits fp8 P x256.
// ---------------------------------------------------------------------------
__global__ void __launch_bounds__(256)
softmax_kernel(const __nv_bfloat16* __restrict__ S, uint8_t* __restrict__ P)
{
    __shared__ float sh[8];
    const size_t rb = (size_t)blockIdx.x * SEQ;
    const int t = threadIdx.x, lane = t & 31, wrp = t >> 5;

    uint4 u0 = *(const uint4*)(S + rb + t * 8);
    uint4 u1 = *(const uint4*)(S + rb + 2048 + t * 8);

    float f[16];
    {
        const uint32_t* w0 = (const uint32_t*)&u0;
        const uint32_t* w1 = (const uint32_t*)&u1;
#pragma unroll
        for (int j = 0; j < 4; ++j) {
            float2 a = __bfloat1622float2(*(const __nv_bfloat162*)&w0[j]);
            f[j*2]   = a.x; f[j*2+1] = a.y;
            float2 b = __bfloat1622float2(*(const __nv_bfloat162*)&w1[j]);
            f[8+j*2] = b.x; f[8+j*2+1] = b.y;
        }
    }

    float mx = -1e30f;
#pragma unroll
    for (int j = 0; j < 16; ++j) mx = fmaxf(mx, f[j]);
#pragma unroll
    for (int o = 16; o > 0; o >>= 1) mx = fmaxf(mx, __shfl_xor_sync(0xffffffffu, mx, o));
    if (lane == 0) sh[wrp] = mx;
    __syncthreads();
    float m_all = sh[0];
#pragma unroll
    for (int w = 1; w < 8; ++w) m_all = fmaxf(m_all, sh[w]);
    __syncthreads();

    float sum = 0.f;
#pragma unroll
    for (int j = 0; j < 16; ++j) {
        f[j] = __expf((f[j] - m_all) * SM_SCALE);
        sum += f[j];
    }
#pragma unroll
    for (int o = 16; o > 0; o >>= 1) sum += __shfl_xor_sync(0xffffffffu, sum, o);
    if (lane == 0) sh[wrp] = sum;
    __syncthreads();
    float s_all = 0.f;
#pragma unroll
    for (int w = 0; w < 8; ++w) s_all += sh[w];
    const float inv = 256.0f / s_all;   // x256 scale folded (PV alpha = 1/256)

    uint2 o0, o1;
    o0.x = pack_f8_4(f[0]*inv,  f[1]*inv,  f[2]*inv,  f[3]*inv);
    o0.y = pack_f8_4(f[4]*inv,  f[5]*inv,  f[6]*inv,  f[7]*inv);
    o1.x = pack_f8_4(f[8]*inv,  f[9]*inv,  f[10]*inv, f[11]*inv);
    o1.y = pack_f8_4(f[12]*inv, f[13]*inv, f[14]*inv, f[15]*inv);
    *(uint2*)(P + rb + t * 8)        = o0;
    *(uint2*)(P + rb + 2048 + t * 8) = o1;
}

// ---------------------------------------------------------------------------
// Residual + LayerNorm over D=1024.
// ---------------------------------------------------------------------------
__global__ void __launch_bounds__(256)
ln_kernel(const float* __restrict__ emb, const float* __restrict__ att,
          const float* __restrict__ gamma, const float* __restrict__ beta,
          float* __restrict__ out)
{
    __shared__ float shs[8];
    __shared__ float shq[8];
    const size_t base = (size_t)blockIdx.x * DIM;
    const int t = threadIdx.x, lane = t & 31, wrp = t >> 5;

    float4 e = *(const float4*)(emb + base + t * 4);
    float4 a = *(const float4*)(att + base + t * 4);
    float4 x;
    x.x = e.x + a.x; x.y = e.y + a.y; x.z = e.z + a.z; x.w = e.w + a.w;

    float s  = x.x + x.y + x.z + x.w;
    float sq = x.x*x.x + x.y*x.y + x.z*x.z + x.w*x.w;
#pragma unroll
    for (int o = 16; o > 0; o >>= 1) {
        s  += __shfl_xor_sync(0xffffffffu, s,  o);
        sq += __shfl_xor_sync(0xffffffffu, sq, o);
    }
    if (lane == 0) { shs[wrp] = s; shq[wrp] = sq; }
    __syncthreads();
    s = 0.f; sq = 0.f;
#pragma unroll
    for (int w = 0; w < 8; ++w) { s += shs[w]; sq += shq[w]; }

    const float mu   = s * (1.0f / (float)DIM);
    const float var  = sq * (1.0f / (float)DIM) - mu * mu;
    const float rstd = rsqrtf(var + LN_EPS);

    float4 g  = *(const float4*)(gamma + t * 4);
    float4 bt = *(const float4*)(beta  + t * 4);
    float4 r;
    r.x = g.x * (x.x - mu) * rstd + bt.x;
    r.y = g.y * (x.y - mu) * rstd + bt.y;
    r.z = g.z * (x.z - mu) * rstd + bt.z;
    r.w = g.w * (x.w - mu) * rstd + bt.w;
    *(float4*)(out + base + t * 4) = r;
}

// ---------------------------------------------------------------------------
// Launch
// ---------------------------------------------------------------------------
extern "C" void kernel_launch(void* const* d_in, const int* in_sizes, int n_in,
                              void* d_out, int out_size)
{
    (void)in_sizes; (void)n_in; (void)out_size;
    const float* emb   = (const float*)d_in[0];
    const float* Wq    = (const float*)d_in[4];
    const float* bq    = (const float*)d_in[5];
    const float* Wk    = (const float*)d_in[6];
    const float* bk    = (const float*)d_in[7];
    const float* Wv    = (const float*)d_in[8];
    const float* bv    = (const float*)d_in[9];
    const float* gamma = (const float*)d_in[10];
    const float* beta  = (const float*)d_in[11];
    float* out = (float*)d_out;

    void* p;
    uint8_t *emb8, *w8, *q8, *k8, *vt8, *p8;
    __nv_bfloat16 *s_b;
    float *att;
    cudaGetSymbolAddress(&p, g_emb8); emb8 = (uint8_t*)p;
    cudaGetSymbolAddress(&p, g_w8);   w8   = (uint8_t*)p;
    cudaGetSymbolAddress(&p, g_q8);   q8   = (uint8_t*)p;
    cudaGetSymbolAddress(&p, g_k8);   k8   = (uint8_t*)p;
    cudaGetSymbolAddress(&p, g_vt8);  vt8  = (uint8_t*)p;
    cudaGetSymbolAddress(&p, g_s_b);  s_b  = (__nv_bfloat16*)p;
    cudaGetSymbolAddress(&p, g_p8);   p8   = (uint8_t*)p;
    cudaGetSymbolAddress(&p, g_att);  att  = (float*)p;

    cudaFuncSetAttribute(gemm_fp8, cudaFuncAttributeMaxDynamicSharedMemorySize, GEMM_SMEM);

    // Convert inputs to fp8: emb (scale 1), weights (scale 32; alpha 1/32 in GEMM)
    const int n8e = MTOT * DIM / 8;
    cvt8_kernel<<<dim3((n8e + 255) / 256, 1, 1), 256>>>(
        (const float4*)emb, (uint2*)emb8, nullptr, nullptr, nullptr, nullptr, 1.0f, n8e);
    const int n8w = DIM * DIM / 8;
    cvt8_kernel<<<dim3((n8w + 255) / 256, 1, 3), 256>>>(
        (const float4*)Wq, (uint2*)(w8),
        (const float4*)Wk, (uint2*)(w8 + (size_t)DIM * DIM),
        (const float4*)Wv, (uint2*)(w8 + (size_t)2 * DIM * DIM), 32.0f, n8w);

    const dim3 blk(256);

    // Q,K projections -> fp8 (alpha 1/32 undoes weight scale)
    const dim3 gq(DIM / TN, MTOT / TM, 1);
    gemm_fp8<<<gq, blk, GEMM_SMEM>>>(emb8, w8,                       bq, 0,
                                     nullptr, nullptr, q8, DIM, DIM, DIM, 1.f/32.f, 0, 0, 0);
    gemm_fp8<<<gq, blk, GEMM_SMEM>>>(emb8, w8 + (size_t)DIM * DIM,   bk, 0,
                                     nullptr, nullptr, k8, DIM, DIM, DIM, 1.f/32.f, 0, 0, 0);

    // V^T: Vt[d][n] = (1/32) * sum_k Wv32[d,k]*emb[n,k] + bv[d] -> fp8
    const dim3 gv(MTOT / TN, DIM / TM, 1);
    gemm_fp8<<<gv, blk, GEMM_SMEM>>>(w8 + (size_t)2 * DIM * DIM, emb8, bv, 1,
                                     nullptr, nullptr, vt8, MTOT, DIM, DIM, 1.f/32.f, 0, 0, 0);

    // Scores: per-batch Q @ K^T -> bf16 (1/sqrt(D) folded into softmax)
    const dim3 gs(SEQ / TN, SEQ / TM, BATCH);
    gemm_fp8<<<gs, blk, GEMM_SMEM>>>(q8, k8, nullptr, 0,
                                     nullptr, s_b, nullptr, SEQ, DIM, DIM, 1.f,
                                     (size_t)SEQ * DIM, (size_t)SEQ * DIM, (size_t)SEQ * SEQ);

    // Softmax rows -> fp8 P (x256)
    softmax_kernel<<<MTOT, 256>>>(s_b, p8);

    // Attended: per-batch P @ V -> fp32 (alpha 1/256 undoes P scale)
    const dim3 gp(DIM / TN, SEQ / TM, BATCH);
    gemm_fp8<<<gp, blk, GEMM_SMEM>>>(p8, vt8, nullptr, 0,
                                     att, nullptr, nullptr, DIM, SEQ, MTOT, 1.f/256.f,
                                     (size_t)SEQ * SEQ, (size_t)SEQ, (size_t)SEQ * DIM);

    // Residual + LayerNorm
    ln_kernel<<<MTOT, 256>>>(emb, att, gamma, beta, out);
}